// round 11
// baseline (speedup 1.0000x reference)
#include <cuda_runtime.h>
#include <cstddef>

#define BATCH 8
#define LFRM  64
#define CH    3
#define HH    224
#define WW    224
#define HWSZ  (HH*WW)            // 50176
#define FRAMES (BATCH*LFRM)      // 512
#define PAIRS  (BATCH*(LFRM-1))  // 504
#define MSEL   16
#define EPSF   1e-6f

#define G      3                 // pairs per block (63 = 21*3)
#define NGRP   (BATCH*21)        // 168 pair-groups
#define NCHUNK 4                 // row chunks per pair
#define CROWS  56                // output rows per chunk
#define INROWS 62                // input rows: 56 + 6 halo

// ---------------- scratch (static device globals; no allocation) -------------
__device__ double g_ds4[PAIRS * NCHUNK];        // per-(pair,chunk) partial diff scores
__device__ int    g_idx[BATCH * MSEL];          // selected frame indices

// ============================================================================
// kernel 1: fused channel-sum + 7x7 box + pairwise |w0*box + eps| reduction
// G=3 pairs per block (4 frames), register-prefetch software pipeline:
// LDGs for bank k+1 are issued before computing bank k, so barriers no longer
// expose DRAM latency.
// ============================================================================
__global__ __launch_bounds__(224) void pairdiff_kernel(const float* __restrict__ x,
                                                       const float* __restrict__ wgt)
{
    __shared__ __align__(16) float buf[2][4][G][232];   // [bank][row][pair][col]
    __shared__ double sd[224];

    const int t     = threadIdx.x;                   // 0..223 (column)
    const int chunk = blockIdx.x;                    // 0..3
    const int grp   = blockIdx.y;                    // 0..167
    const int b     = grp / 21;
    const int l0    = (grp % 21) * G;
    const int r0    = chunk * CROWS;

    const float w0 = __ldg(wgt);                     // uniform conv weight
    const float* xf = x + (size_t)(b * LFRM + l0) * (CH * HWSZ);  // frames l0..l0+3

    // zero halo columns of all row buffers
    if (t < 6) {
        const int pc = (t < 3) ? t : 224 + t;        // 0,1,2,227,228,229
        for (int bk = 0; bk < 2; bk++)
            for (int e = 0; e < 4; e++)
                for (int p = 0; p < G; p++) buf[bk][e][p][pc] = 0.f;
    }
    __syncthreads();

    float rv[4][12];                                 // prefetch regs: [row][frame*3+ch]

    auto issue_loads = [&](int k) {
#pragma unroll
        for (int e = 0; e < 4; e++) {
            const int j = 4 * k + e;
            const int i = r0 - 3 + j;
            const bool ok = ((unsigned)i < (unsigned)HH) && (j < INROWS);
            const float* p = xf + (size_t)i * WW + t;
#pragma unroll
            for (int q = 0; q < 12; q++)
                rv[e][q] = ok ? __ldg(p + (size_t)q * HWSZ) : 0.f;
        }
    };

    auto store_bank = [&](int bank) {
#pragma unroll
        for (int e = 0; e < 4; e++) {
            float s0 = (rv[e][0] + rv[e][1])  + rv[e][2];
            float s1 = (rv[e][3] + rv[e][4])  + rv[e][5];
            float s2 = (rv[e][6] + rv[e][7])  + rv[e][8];
            float s3 = (rv[e][9] + rv[e][10]) + rv[e][11];
            buf[bank][e][0][3 + t] = s0 - s1;
            buf[bank][e][1][3 + t] = s1 - s2;
            buf[bank][e][2][3 + t] = s2 - s3;
        }
    };

    float hb[G][8];                                  // hbox register rings
#pragma unroll
    for (int p = 0; p < G; p++)
#pragma unroll
        for (int k = 0; k < 8; k++) hb[p][k] = 0.f;
    double acc[G][2];
#pragma unroll
    for (int p = 0; p < G; p++) { acc[p][0] = 0.0; acc[p][1] = 0.0; }

    auto compute_bank = [&](int bank, int k) {
#pragma unroll
        for (int e = 0; e < 4; e++) {
            const int j  = 4 * k + e;
            const int re = bank * 4 + e;             // == j mod 8 (static slot)
#pragma unroll
            for (int p = 0; p < G; p++) {
                const float* rp = &buf[bank][e][p][t];       // cols t-3..t+3
                hb[p][re] = ((rp[0] + rp[1]) + (rp[2] + rp[3]))
                          + ((rp[4] + rp[5]) + rp[6]);
            }
            if (j >= 6 && j < 6 + CROWS) {           // output row r0 + j - 6
#pragma unroll
                for (int p = 0; p < G; p++) {
                    float vs = ((hb[p][(re)     & 7] + hb[p][(re + 7) & 7])
                             +  (hb[p][(re + 6) & 7] + hb[p][(re + 5) & 7]))
                             + ((hb[p][(re + 4) & 7] + hb[p][(re + 3) & 7])
                             +   hb[p][(re + 2) & 7]);
                    acc[p][e & 1] += (double)fabsf(fmaf(w0, vs, EPSF));
                }
            }
        }
    };

    // ---- pipelined main loop: 16 banks of 4 rows (j = 0..63, valid < 62) ----
    issue_loads(0);
#pragma unroll 1
    for (int k = 0; k < 16; k++) {
        const int bank = k & 1;
        store_bank(bank);
        __syncthreads();
        if (k < 15) issue_loads(k + 1);   // in flight during compute below
        compute_bank(bank, k);
        __syncthreads();
    }

    // ---- block reduction of double partials, per pair ----
#pragma unroll 1
    for (int p = 0; p < G; p++) {
        sd[t] = acc[p][0] + acc[p][1];
        __syncthreads();
        if (t < 112) sd[t] += sd[t + 112];
        __syncthreads();
        if (t < 56)  sd[t] += sd[t + 56];
        __syncthreads();
        if (t < 28)  sd[t] += sd[t + 28];
        __syncthreads();
        if (t < 14)  sd[t] += sd[t + 14];
        __syncthreads();
        if (t < 7)   sd[t] += sd[t + 7];
        __syncthreads();
        if (t == 0) {
            double s = sd[0];
            for (int q = 1; q < 7; q++) s += sd[q];
            g_ds4[(b * (LFRM - 1) + l0 + p) * NCHUNK + chunk] = s;
        }
        __syncthreads();
    }
}

// ---------------- kernel 2: sqrt / normalize / cumsum / argmin (parallel) ----
__global__ __launch_bounds__(512) void select_kernel()
{
    __shared__ double dsp[PAIRS];
    __shared__ double cum[PAIRS];
    const int t = threadIdx.x;

    if (t < PAIRS) {
        const double* q = &g_ds4[t * NCHUNK];
        dsp[t] = sqrt((q[0] + q[1]) + (q[2] + q[3]));
    }
    __syncthreads();

    if (t < BATCH) {
        const double* dp = &dsp[t * (LFRM - 1)];
        double s = 0.0;
        for (int l = 0; l < LFRM - 1; l++) s += dp[l];
        const double inv = 1.0 / s;
        double c = 0.0;
        for (int l = 0; l < LFRM - 1; l++) {
            c += dp[l] * inv;
            cum[t * (LFRM - 1) + l] = c;
        }
    }
    __syncthreads();

    if (t < BATCH * MSEL) {
        const int b = t >> 4, m = t & 15;
        const double* cp = &cum[b * (LFRM - 1)];
        const float interval = 1.0f / (float)(MSEL - 1);
        const double target = (double)((float)m * interval);
        double best = 1e300;
        int bi = 0;
        for (int l = 0; l < LFRM - 1; l++) {
            double d = fabs(cp[l] - target);
            if (d < best) { best = d; bi = l; }   // strict '<' => first occurrence
        }
        g_idx[t] = bi;
    }
}

// ---------------- kernel 3: gather selected frames ---------------------------
__global__ __launch_bounds__(256) void gather_kernel(const float* __restrict__ x,
                                                     float* __restrict__ out)
{
    const int bm = blockIdx.y;             // 0..127
    const int b  = bm >> 4;
    const int src = b * LFRM + g_idx[bm];
    const float4* sp = (const float4*)(x + (size_t)src * (CH * HWSZ));
    float4* dp = (float4*)(out + (size_t)bm * (CH * HWSZ));
    const int i = blockIdx.x * 256 + threadIdx.x;   // 147*256 = 37632 exact
    dp[i] = sp[i];
}

// ---------------- launcher ---------------------------------------------------
extern "C" void kernel_launch(void* const* d_in, const int* in_sizes, int n_in,
                              void* d_out, int out_size)
{
    const float* x = nullptr;
    const float* w = nullptr;
    for (int i = 0; i < n_in; i++) {
        if (in_sizes[i] == FRAMES * CH * HWSZ) x = (const float*)d_in[i];
        else if (in_sizes[i] == CH * 49)       w = (const float*)d_in[i];
    }

    pairdiff_kernel<<<dim3(NCHUNK, NGRP), 224>>>(x, w);
    select_kernel<<<1, 512>>>();
    gather_kernel<<<dim3(147, BATCH * MSEL), 256>>>(x, (float*)d_out);
}

// round 12
// speedup vs baseline: 1.1269x; 1.1269x over previous
#include <cuda_runtime.h>
#include <cstddef>

#define BATCH 8
#define LFRM  64
#define CH    3
#define HH    224
#define WW    224
#define HWSZ  (HH*WW)            // 50176
#define FRAMES (BATCH*LFRM)      // 512
#define PAIRS  (BATCH*(LFRM-1))  // 504
#define MSEL   16
#define EPSF   1e-6f

#define G      3                 // pairs per block (63 = 21*3)
#define NGRP   (BATCH*21)        // 168 pair-groups
#define NCHUNK 8                 // row chunks per pair
#define CROWS  28                // output rows per chunk (8*28 = 224)
#define INROWS 34                // input rows: 28 + 6 halo
#define NPH    9                 // ceil(34/4) phases of 4 rows

// ---------------- scratch (static device globals; no allocation) -------------
__device__ double g_ds4[PAIRS * NCHUNK];        // per-(pair,chunk) partial diff scores
__device__ int    g_idx[BATCH * MSEL];          // selected frame indices

// ============================================================================
// kernel 1: fused channel-sum + 7x7 box + pairwise |w0*box + eps| reduction
// G=3 pairs per block (4 frames). Store phase: thread = (row, 4-col segment),
// 12x LDG.128 -> channel sums -> 3 diff float4 -> STS.128 (transient regs only).
// Compute phase: thread = column, hbox from smem + vertical register ring.
// Double-banked smem, ONE barrier per phase.
// ============================================================================
__global__ __launch_bounds__(224, 6) void pairdiff_kernel(const float* __restrict__ x,
                                                          const float* __restrict__ wgt)
{
    __shared__ __align__(16) float buf[2][4][G][232];   // [bank][row][pair][4+col]
    __shared__ double sd[224];

    const int t     = threadIdx.x;                   // 0..223
    const int chunk = blockIdx.x;                    // 0..7
    const int grp   = blockIdx.y;                    // 0..167
    const int b     = grp / 21;
    const int l0    = (grp % 21) * G;
    const int r0    = chunk * CROWS;

    const float w0 = __ldg(wgt);                     // uniform conv weight
    const float* xf = x + (size_t)(b * LFRM + l0) * (CH * HWSZ);  // frames l0..l0+3

    // zero halo columns (indices 0..3 and 228..231) of all row buffers
    if (t < 8) {
        const int pc = (t < 4) ? t : 224 + t;        // 0..3, 228..231
        for (int bk = 0; bk < 2; bk++)
            for (int e = 0; e < 4; e++)
                for (int p = 0; p < G; p++) buf[bk][e][p][pc] = 0.f;
    }
    __syncthreads();

    // store-phase mapping: row e = t/56, segment s = t%56 (cols 4s..4s+3)
    const int se = t / 56;
    const int ss = t - se * 56;

    float hb[G][8];                                  // hbox register rings
#pragma unroll
    for (int p = 0; p < G; p++)
#pragma unroll
        for (int k = 0; k < 8; k++) hb[p][k] = 0.f;
    double acc[G][2];
#pragma unroll
    for (int p = 0; p < G; p++) { acc[p][0] = 0.0; acc[p][1] = 0.0; }

#pragma unroll 1
    for (int k = 0; k < NPH; k++) {
        const int bank = k & 1;

        // ---- store phase: one (row, segment) per thread ----
        {
            const int j = 4 * k + se;
            const int i = r0 - 3 + j;
            const bool ok = ((unsigned)i < (unsigned)HH) && (j < INROWS);
            const float* rowp = xf + (ptrdiff_t)i * WW + 4 * ss;
            float4 z = make_float4(0.f, 0.f, 0.f, 0.f);

            // frame channel-sum: ((c0 + c1) + c2), matching scalar tree
            float4 s0 = z, s1 = z, s2 = z, s3 = z;
            if (ok) {
                float4 a, bb, c;
                a  = __ldg((const float4*)(rowp));
                bb = __ldg((const float4*)(rowp + (size_t)1 * HWSZ));
                c  = __ldg((const float4*)(rowp + (size_t)2 * HWSZ));
                s0 = make_float4((a.x + bb.x) + c.x, (a.y + bb.y) + c.y,
                                 (a.z + bb.z) + c.z, (a.w + bb.w) + c.w);
                a  = __ldg((const float4*)(rowp + (size_t)3 * HWSZ));
                bb = __ldg((const float4*)(rowp + (size_t)4 * HWSZ));
                c  = __ldg((const float4*)(rowp + (size_t)5 * HWSZ));
                s1 = make_float4((a.x + bb.x) + c.x, (a.y + bb.y) + c.y,
                                 (a.z + bb.z) + c.z, (a.w + bb.w) + c.w);
            }
            float4 d01 = make_float4(s0.x - s1.x, s0.y - s1.y, s0.z - s1.z, s0.w - s1.w);
            *(float4*)&buf[bank][se][0][4 + 4 * ss] = d01;

            if (ok) {
                float4 a, bb, c;
                a  = __ldg((const float4*)(rowp + (size_t)6 * HWSZ));
                bb = __ldg((const float4*)(rowp + (size_t)7 * HWSZ));
                c  = __ldg((const float4*)(rowp + (size_t)8 * HWSZ));
                s2 = make_float4((a.x + bb.x) + c.x, (a.y + bb.y) + c.y,
                                 (a.z + bb.z) + c.z, (a.w + bb.w) + c.w);
            }
            float4 d12 = make_float4(s1.x - s2.x, s1.y - s2.y, s1.z - s2.z, s1.w - s2.w);
            *(float4*)&buf[bank][se][1][4 + 4 * ss] = d12;

            if (ok) {
                float4 a, bb, c;
                a  = __ldg((const float4*)(rowp + (size_t)9  * HWSZ));
                bb = __ldg((const float4*)(rowp + (size_t)10 * HWSZ));
                c  = __ldg((const float4*)(rowp + (size_t)11 * HWSZ));
                s3 = make_float4((a.x + bb.x) + c.x, (a.y + bb.y) + c.y,
                                 (a.z + bb.z) + c.z, (a.w + bb.w) + c.w);
            }
            float4 d23 = make_float4(s2.x - s3.x, s2.y - s3.y, s2.z - s3.z, s2.w - s3.w);
            *(float4*)&buf[bank][se][2][4 + 4 * ss] = d23;
        }
        __syncthreads();     // single barrier per phase (double-buffer safe)

        // ---- compute phase: thread = column t ----
#pragma unroll
        for (int e = 0; e < 4; e++) {
            const int j  = 4 * k + e;
            const int re = bank * 4 + e;             // == j mod 8 (static slot)
#pragma unroll
            for (int p = 0; p < G; p++) {
                const float* rp = &buf[bank][e][p][t + 1];   // cols t-3..t+3
                hb[p][re] = ((rp[0] + rp[1]) + (rp[2] + rp[3]))
                          + ((rp[4] + rp[5]) + rp[6]);
            }
            if (j >= 6 && j < 6 + CROWS) {           // output row r0 + j - 6
#pragma unroll
                for (int p = 0; p < G; p++) {
                    float vs = ((hb[p][(re)     & 7] + hb[p][(re + 7) & 7])
                             +  (hb[p][(re + 6) & 7] + hb[p][(re + 5) & 7]))
                             + ((hb[p][(re + 4) & 7] + hb[p][(re + 3) & 7])
                             +   hb[p][(re + 2) & 7]);
                    acc[p][e & 1] += (double)fabsf(fmaf(w0, vs, EPSF));
                }
            }
        }
    }

    // ---- block reduction of double partials, per pair ----
#pragma unroll 1
    for (int p = 0; p < G; p++) {
        __syncthreads();
        sd[t] = acc[p][0] + acc[p][1];
        __syncthreads();
        if (t < 112) sd[t] += sd[t + 112];
        __syncthreads();
        if (t < 56)  sd[t] += sd[t + 56];
        __syncthreads();
        if (t < 28)  sd[t] += sd[t + 28];
        __syncthreads();
        if (t < 14)  sd[t] += sd[t + 14];
        __syncthreads();
        if (t < 7)   sd[t] += sd[t + 7];
        __syncthreads();
        if (t == 0) {
            double s = sd[0];
            for (int q = 1; q < 7; q++) s += sd[q];
            g_ds4[(b * (LFRM - 1) + l0 + p) * NCHUNK + chunk] = s;
        }
    }
}

// ---------------- kernel 2: sqrt / normalize / cumsum / argmin (parallel) ----
__global__ __launch_bounds__(512) void select_kernel()
{
    __shared__ double dsp[PAIRS];
    __shared__ double cum[PAIRS];
    const int t = threadIdx.x;

    if (t < PAIRS) {
        const double* q = &g_ds4[t * NCHUNK];
        dsp[t] = sqrt((((q[0] + q[1]) + (q[2] + q[3]))
                     + ((q[4] + q[5]) + (q[6] + q[7]))));
    }
    __syncthreads();

    if (t < BATCH) {
        const double* dp = &dsp[t * (LFRM - 1)];
        double s = 0.0;
        for (int l = 0; l < LFRM - 1; l++) s += dp[l];
        const double inv = 1.0 / s;
        double c = 0.0;
        for (int l = 0; l < LFRM - 1; l++) {
            c += dp[l] * inv;
            cum[t * (LFRM - 1) + l] = c;
        }
    }
    __syncthreads();

    if (t < BATCH * MSEL) {
        const int b = t >> 4, m = t & 15;
        const double* cp = &cum[b * (LFRM - 1)];
        const float interval = 1.0f / (float)(MSEL - 1);
        const double target = (double)((float)m * interval);
        double best = 1e300;
        int bi = 0;
        for (int l = 0; l < LFRM - 1; l++) {
            double d = fabs(cp[l] - target);
            if (d < best) { best = d; bi = l; }   // strict '<' => first occurrence
        }
        g_idx[t] = bi;
    }
}

// ---------------- kernel 3: gather selected frames ---------------------------
__global__ __launch_bounds__(256) void gather_kernel(const float* __restrict__ x,
                                                     float* __restrict__ out)
{
    const int bm = blockIdx.y;             // 0..127
    const int b  = bm >> 4;
    const int src = b * LFRM + g_idx[bm];
    const float4* sp = (const float4*)(x + (size_t)src * (CH * HWSZ));
    float4* dp = (float4*)(out + (size_t)bm * (CH * HWSZ));
    const int i = blockIdx.x * 256 + threadIdx.x;   // 147*256 = 37632 exact
    dp[i] = sp[i];
}

// ---------------- launcher ---------------------------------------------------
extern "C" void kernel_launch(void* const* d_in, const int* in_sizes, int n_in,
                              void* d_out, int out_size)
{
    const float* x = nullptr;
    const float* w = nullptr;
    for (int i = 0; i < n_in; i++) {
        if (in_sizes[i] == FRAMES * CH * HWSZ) x = (const float*)d_in[i];
        else if (in_sizes[i] == CH * 49)       w = (const float*)d_in[i];
    }

    pairdiff_kernel<<<dim3(NCHUNK, NGRP), 224>>>(x, w);
    select_kernel<<<1, 512>>>();
    gather_kernel<<<dim3(147, BATCH * MSEL), 256>>>(x, (float*)d_out);
}